// round 11
// baseline (speedup 1.0000x reference)
#include <cuda_runtime.h>
#include <stdint.h>
#include <math.h>

// Mixtral sparse MoE, GB300 sm_103a. T=2048, H=1024, E=8, F=2816, top-2.
// mma.sync tf32 path (tcgen05 rejected by harness ptxas target sm_103).
constexpr int T = 2048, H = 1024, E = 8, F = 2816;
constexpr int AMAX = 2 * T, APAD = AMAX + 256;

__device__ uint32_t g_xg[(size_t)APAD * H];    // gathered tokens, tf32 bits
__device__ uint32_t g_act[(size_t)APAD * F];   // SwiGLU activations, tf32 bits
__device__ float    g_y[(size_t)AMAX * H];     // per-slot down proj
__device__ int   g_cnt[E], g_off[E], g_cur[E];
__device__ int   g_top_e[T * 2];
__device__ float g_top_w[T * 2];
__device__ int   g_assign_tok[AMAX];
__device__ float g_assign_w[AMAX];
__device__ int   g_tok2slot[T * 2];
__device__ float g_logits_dummy[T * E];

// ---------------- helpers ----------------
__device__ __forceinline__ uint32_t f2tf32(float f) {
    uint32_t u; asm("cvt.rna.tf32.f32 %0, %1;" : "=r"(u) : "f"(f)); return u;
}
__device__ __forceinline__ uint32_t t32(uint32_t raw) {  // raw f32 bits -> tf32 rna
    uint32_t u; asm("cvt.rna.tf32.f32 %0, %1;" : "=r"(u) : "f"(__uint_as_float(raw))); return u;
}
__device__ __forceinline__ void mma_tf32(float* c, const uint32_t* a, const uint32_t* b) {
    asm volatile(
        "mma.sync.aligned.m16n8k8.row.col.f32.tf32.tf32.f32 "
        "{%0,%1,%2,%3}, {%4,%5,%6,%7}, {%8,%9}, {%0,%1,%2,%3};\n"
        : "+f"(c[0]), "+f"(c[1]), "+f"(c[2]), "+f"(c[3])
        : "r"(a[0]), "r"(a[1]), "r"(a[2]), "r"(a[3]), "r"(b[0]), "r"(b[1]));
}
__device__ __forceinline__ uint32_t smem_u32(const void* p) {
    uint32_t a;
    asm("{ .reg .u64 t; cvta.to.shared.u64 t, %1; cvt.u32.u64 %0, t; }" : "=r"(a) : "l"(p));
    return a;
}
__device__ __forceinline__ void cpa16(uint32_t dst, const void* src) {
    asm volatile("cp.async.cg.shared.global [%0], [%1], 16;" :: "r"(dst), "l"(src));
}
__device__ __forceinline__ void cp_commit() { asm volatile("cp.async.commit_group;"); }
template <int N> __device__ __forceinline__ void cp_wait() {
    asm volatile("cp.async.wait_group %0;" :: "n"(N));
}

// ---------------- small kernels ----------------
__global__ void zero_counts_kernel() { if (threadIdx.x < E) g_cnt[threadIdx.x] = 0; }

__global__ __launch_bounds__(256) void router_kernel(
    const float* __restrict__ x, const float* __restrict__ gw, float* __restrict__ logits_out) {
    __shared__ float sgw[E * H];
    int tid = threadIdx.x;
    for (int i = tid; i < E * H; i += 256) sgw[i] = gw[i];
    __syncthreads();
    int warp = tid >> 5, lane = tid & 31;
    int t = blockIdx.x * 8 + warp;
    float xr[32];
    const float* xp = x + (size_t)t * H;
#pragma unroll
    for (int i = 0; i < 32; i++) xr[i] = xp[i * 32 + lane];
    float l[E];
#pragma unroll
    for (int e = 0; e < E; e++) {
        float acc = 0.f;
        const float* g = sgw + e * H;
#pragma unroll
        for (int i = 0; i < 32; i++) acc += xr[i] * g[i * 32 + lane];
#pragma unroll
        for (int o = 16; o > 0; o >>= 1) acc += __shfl_xor_sync(0xffffffffu, acc, o);
        l[e] = acc;
    }
    if (lane == 0) {
#pragma unroll
        for (int e = 0; e < E; e++) logits_out[(size_t)t * E + e] = l[e];
        int e0 = 0; float b0 = l[0];
#pragma unroll
        for (int e = 1; e < E; e++) if (l[e] > b0) { b0 = l[e]; e0 = e; }
        int e1 = (e0 == 0) ? 1 : 0; float b1 = l[e1];
#pragma unroll
        for (int e = 0; e < E; e++) if (e != e0 && l[e] > b1) { b1 = l[e]; e1 = e; }
        float p = expf(b1 - b0), inv = 1.f / (1.f + p);
        g_top_e[2 * t] = e0;     g_top_w[2 * t] = inv;
        g_top_e[2 * t + 1] = e1; g_top_w[2 * t + 1] = p * inv;
        atomicAdd(&g_cnt[e0], 1);
        atomicAdd(&g_cnt[e1], 1);
    }
}

__global__ void scan_kernel() {
    int off = 0;
    for (int e = 0; e < E; e++) { g_off[e] = off; g_cur[e] = off; off += g_cnt[e]; }
}

__global__ void assign_kernel() {
    int t = blockIdx.x * blockDim.x + threadIdx.x;
    if (t >= T) return;
#pragma unroll
    for (int k = 0; k < 2; k++) {
        int e = g_top_e[2 * t + k];
        int slot = atomicAdd(&g_cur[e], 1);
        g_assign_tok[slot] = t;
        g_assign_w[slot] = g_top_w[2 * t + k];
        g_tok2slot[2 * t + k] = slot;
    }
}

__global__ void gather_kernel(const float* __restrict__ x) {
    int slot = blockIdx.x;
    int tok = g_assign_tok[slot];
    float4 f = ((const float4*)(x + (size_t)tok * H))[threadIdx.x];
    ((uint4*)(g_xg + (size_t)slot * H))[threadIdx.x] =
        make_uint4(f2tf32(f.x), f2tf32(f.y), f2tf32(f.z), f2tf32(f.w));
}

// ---------------------------------------------------------------------------
// GEMM1: act = rw * silu(X@w1) * (X@w3)
// CTA 512 thr = 16 warps (4x4), tile M=128 x N=128, K-stage 32, 3-stage cp.async.
// Warp tile 32x32 per matrix. A (g_xg) already tf32; B rounded post-LDS.
// SMEM: A[3][128*36] | B1[3][32*136] | B3[3][32*136]  (~160 KB)
// ---------------------------------------------------------------------------
constexpr int STG = 3;
constexpr int A_W  = 128 * 36;
constexpr int B_W  = 32 * 136;
constexpr int G1_SMEM = (STG * A_W + STG * 2 * B_W) * 4;

__global__ void __launch_bounds__(512, 1) gemm1_kernel(
    const float* __restrict__ w1, const float* __restrict__ w3) {
    const int e = blockIdx.z, mt = blockIdx.y;
    const int cnt = g_cnt[e];
    if (mt * 128 >= cnt) return;
    const int off = g_off[e];
    const int n0 = blockIdx.x * 128;

    extern __shared__ uint32_t sm[];
    const uint32_t sb = smem_u32(sm);
    __shared__ float swt[128];

    const int tid = threadIdx.x;
    if (tid < 128) {
        int r = mt * 128 + tid;
        swt[tid] = (r < cnt) ? g_assign_w[off + r] : 0.f;
    }

    const uint32_t* Asrc = g_xg + (size_t)(off + mt * 128) * H;
    const float* w1p = w1 + (size_t)e * H * F + n0;
    const float* w3p = w3 + (size_t)e * H * F + n0;

    auto stage = [&](int s, int k0) {
        const uint32_t ab  = sb + (s * A_W) * 4;
        const uint32_t b1b = sb + (STG * A_W + s * B_W) * 4;
        const uint32_t b3b = sb + (STG * A_W + (STG + s) * B_W) * 4;
#pragma unroll
        for (int v = 0; v < 2; v++) {                       // A: 128x32 words
            int idx = tid + v * 512;
            int row = idx >> 3, c4 = (idx & 7) << 2;
            cpa16(ab + (row * 36 + c4) * 4, Asrc + (size_t)row * H + k0 + c4);
        }
#pragma unroll
        for (int v = 0; v < 2; v++) {                       // B: 32x128 words x2
            int idx = tid + v * 512;
            int row = idx >> 5, c4 = (idx & 31) << 2;
            size_t g = (size_t)(k0 + row) * F + c4;
            cpa16(b1b + (row * 136 + c4) * 4, w1p + g);
            cpa16(b3b + (row * 136 + c4) * 4, w3p + g);
        }
        cp_commit();
    };

    const int lane = tid & 31, warp = tid >> 5;
    const int wm = warp >> 2, wn = warp & 3;    // 4x4 warp grid
    const int lr = lane >> 2, lc = lane & 3;

    float accG[2][4][4], accU[2][4][4];
#pragma unroll
    for (int i = 0; i < 2; i++)
#pragma unroll
        for (int j = 0; j < 4; j++)
#pragma unroll
            for (int c = 0; c < 4; c++) { accG[i][j][c] = 0.f; accU[i][j][c] = 0.f; }

    stage(0, 0);
    stage(1, 32);

    const int NK = H / 32;  // 32
    for (int i = 0; i < NK; i++) {
        cp_wait<STG - 2>();
        __syncthreads();
        int kn = i + STG - 1;
        if (kn < NK) stage(kn % STG, kn * 32);
        else cp_commit();

        int s = i % STG;
        const uint32_t* As  = sm + s * A_W;
        const uint32_t* Bs1 = sm + STG * A_W + s * B_W;
        const uint32_t* Bs3 = sm + STG * A_W + (STG + s) * B_W;
#pragma unroll
        for (int kk = 0; kk < 4; kk++) {
            uint32_t a[2][4];
#pragma unroll
            for (int mi = 0; mi < 2; mi++) {
                int r0 = wm * 32 + mi * 16 + lr, cA = kk * 8 + lc;
                a[mi][0] = As[r0 * 36 + cA];
                a[mi][1] = As[(r0 + 8) * 36 + cA];
                a[mi][2] = As[r0 * 36 + cA + 4];
                a[mi][3] = As[(r0 + 8) * 36 + cA + 4];
            }
#pragma unroll
            for (int ni = 0; ni < 4; ni++) {
                int col = wn * 32 + ni * 8 + lr, rB = kk * 8 + lc;
                uint32_t b1[2] = { t32(Bs1[rB * 136 + col]), t32(Bs1[(rB + 4) * 136 + col]) };
                uint32_t b3[2] = { t32(Bs3[rB * 136 + col]), t32(Bs3[(rB + 4) * 136 + col]) };
#pragma unroll
                for (int mi = 0; mi < 2; mi++) {
                    mma_tf32(accG[mi][ni], a[mi], b1);
                    mma_tf32(accU[mi][ni], a[mi], b3);
                }
            }
        }
    }

    // epilogue: act = rw * u * silu(g), stored tf32 (GEMM2 reads raw)
#pragma unroll
    for (int mi = 0; mi < 2; mi++)
#pragma unroll
        for (int hf = 0; hf < 2; hf++) {
            int row = wm * 32 + mi * 16 + lr + hf * 8;
            int grow = mt * 128 + row;
            if (grow < cnt) {
                float w = swt[row];
                uint32_t* dst = g_act + (size_t)(off + grow) * F + n0;
#pragma unroll
                for (int ni = 0; ni < 4; ni++) {
                    int col = wn * 32 + ni * 8 + lc * 2;
                    float gg = accG[mi][ni][hf * 2], uu = accU[mi][ni][hf * 2];
                    float a0 = w * uu * (gg / (1.f + expf(-gg)));
                    gg = accG[mi][ni][hf * 2 + 1]; uu = accU[mi][ni][hf * 2 + 1];
                    float a1 = w * uu * (gg / (1.f + expf(-gg)));
                    *(uint2*)(dst + col) = make_uint2(f2tf32(a0), f2tf32(a1));
                }
            }
        }
}

// ---------------------------------------------------------------------------
// GEMM2: y = act @ w2[e]; 512 thr, tile 128x128, warp 4x4 (32x32), K=2816.
// SMEM: A[3][128*36] | B[3][32*136]  (~107.5 KB)
// ---------------------------------------------------------------------------
constexpr int G2_SMEM = (STG * A_W + STG * B_W) * 4;

__global__ void __launch_bounds__(512, 1) gemm2_kernel(const float* __restrict__ w2) {
    const int e = blockIdx.z, mt = blockIdx.y;
    const int cnt = g_cnt[e];
    if (mt * 128 >= cnt) return;
    const int off = g_off[e];
    const int n0 = blockIdx.x * 128;

    extern __shared__ uint32_t sm[];
    const uint32_t sb = smem_u32(sm);
    const int tid = threadIdx.x;

    const uint32_t* Asrc = g_act + (size_t)(off + mt * 128) * F;
    const float* Wp = w2 + (size_t)e * F * H + n0;

    auto stage = [&](int s, int k0) {
        const uint32_t ab = sb + (s * A_W) * 4;
        const uint32_t bb = sb + (STG * A_W + s * B_W) * 4;
#pragma unroll
        for (int v = 0; v < 2; v++) {
            int idx = tid + v * 512;
            int row = idx >> 3, c4 = (idx & 7) << 2;
            cpa16(ab + (row * 36 + c4) * 4, Asrc + (size_t)row * F + k0 + c4);
        }
#pragma unroll
        for (int v = 0; v < 2; v++) {
            int idx = tid + v * 512;
            int row = idx >> 5, c4 = (idx & 31) << 2;
            cpa16(bb + (row * 136 + c4) * 4, Wp + (size_t)(k0 + row) * H + c4);
        }
        cp_commit();
    };

    const int lane = tid & 31, warp = tid >> 5;
    const int wm = warp >> 2, wn = warp & 3;
    const int lr = lane >> 2, lc = lane & 3;

    float acc[2][4][4];
#pragma unroll
    for (int i = 0; i < 2; i++)
#pragma unroll
        for (int j = 0; j < 4; j++)
#pragma unroll
            for (int c = 0; c < 4; c++) acc[i][j][c] = 0.f;

    stage(0, 0);
    stage(1, 32);

    const int NK = F / 32;  // 88
    for (int i = 0; i < NK; i++) {
        cp_wait<STG - 2>();
        __syncthreads();
        int kn = i + STG - 1;
        if (kn < NK) stage(kn % STG, kn * 32);
        else cp_commit();

        int s = i % STG;
        const uint32_t* As = sm + s * A_W;
        const uint32_t* Bs = sm + STG * A_W + s * B_W;
#pragma unroll
        for (int kk = 0; kk < 4; kk++) {
            uint32_t a[2][4];
#pragma unroll
            for (int mi = 0; mi < 2; mi++) {
                int r0 = wm * 32 + mi * 16 + lr, cA = kk * 8 + lc;
                a[mi][0] = As[r0 * 36 + cA];
                a[mi][1] = As[(r0 + 8) * 36 + cA];
                a[mi][2] = As[r0 * 36 + cA + 4];
                a[mi][3] = As[(r0 + 8) * 36 + cA + 4];
            }
#pragma unroll
            for (int ni = 0; ni < 4; ni++) {
                int col = wn * 32 + ni * 8 + lr, rB = kk * 8 + lc;
                uint32_t b[2] = { t32(Bs[rB * 136 + col]), t32(Bs[(rB + 4) * 136 + col]) };
#pragma unroll
                for (int mi = 0; mi < 2; mi++) mma_tf32(acc[mi][ni], a[mi], b);
            }
        }
    }

#pragma unroll
    for (int mi = 0; mi < 2; mi++)
#pragma unroll
        for (int hf = 0; hf < 2; hf++) {
            int row = wm * 32 + mi * 16 + lr + hf * 8;
            int grow = mt * 128 + row;
            if (grow < cnt) {
                float* dst = g_y + (size_t)(off + grow) * H + n0;
#pragma unroll
                for (int ni = 0; ni < 4; ni++) {
                    int col = wn * 32 + ni * 8 + lc * 2;
                    *(float2*)(dst + col) =
                        make_float2(acc[mi][ni][hf * 2], acc[mi][ni][hf * 2 + 1]);
                }
            }
        }
}

// ---------------- combine ----------------
__global__ void combine_kernel(float* __restrict__ out) {
    int t = blockIdx.x;
    int s0 = g_tok2slot[2 * t], s1 = g_tok2slot[2 * t + 1];
    float4 a = ((const float4*)(g_y + (size_t)s0 * H))[threadIdx.x];
    float4 b = ((const float4*)(g_y + (size_t)s1 * H))[threadIdx.x];
    ((float4*)(out + (size_t)t * H))[threadIdx.x] =
        make_float4(a.x + b.x, a.y + b.y, a.z + b.z, a.w + b.w);
}

// ---------------- launch ----------------
extern "C" void kernel_launch(void* const* d_in, const int* in_sizes, int n_in,
                              void* d_out, int out_size) {
    const float* x  = (const float*)d_in[0];
    const float* gw = (const float*)d_in[1];
    const float* w1 = (const float*)d_in[2];
    const float* w3 = (const float*)d_in[3];
    const float* w2 = (const float*)d_in[4];
    float* out = (float*)d_out;

    float* logits;
    if (out_size >= T * H + T * E) logits = out + (size_t)T * H;
    else cudaGetSymbolAddress((void**)&logits, g_logits_dummy);

    cudaFuncSetAttribute(gemm1_kernel, cudaFuncAttributeMaxDynamicSharedMemorySize, G1_SMEM);
    cudaFuncSetAttribute(gemm2_kernel, cudaFuncAttributeMaxDynamicSharedMemorySize, G2_SMEM);

    zero_counts_kernel<<<1, 32>>>();
    router_kernel<<<T / 8, 256>>>(x, gw, logits);
    scan_kernel<<<1, 1>>>();
    assign_kernel<<<(T + 255) / 256, 256>>>();
    gather_kernel<<<AMAX, 256>>>(x);
    gemm1_kernel<<<dim3(F / 128, 16, E), 512, G1_SMEM>>>(w1, w3);
    gemm2_kernel<<<dim3(H / 128, 16, E), 512, G2_SMEM>>>(w2);
    combine_kernel<<<T, 256>>>(out);
}

// round 12
// speedup vs baseline: 1.3784x; 1.3784x over previous
#include <cuda_runtime.h>
#include <cuda_fp16.h>
#include <stdint.h>
#include <math.h>

// Mixtral sparse MoE, GB300 sm_103a. T=2048, H=1024, E=8, F=2816, top-2.
// fp16 mma.sync m16n8k16 path (fp32 accum). tcgen05 blocked by harness ptxas.
constexpr int T = 2048, H = 1024, E = 8, F = 2816;
constexpr int AMAX = 2 * T, APAD = AMAX + 256;

__device__ __half g_xh[(size_t)APAD * H];     // gathered tokens, fp16
__device__ __half g_acth[(size_t)APAD * F];   // SwiGLU activations, fp16
__device__ float  g_y[(size_t)AMAX * H];      // per-slot down proj
__device__ int   g_cnt[E], g_off[E], g_cur[E];
__device__ int   g_top_e[T * 2];
__device__ float g_top_w[T * 2];
__device__ int   g_assign_tok[AMAX];
__device__ float g_assign_w[AMAX];
__device__ int   g_tok2slot[T * 2];
__device__ float g_logits_dummy[T * E];

// ---------------- helpers ----------------
__device__ __forceinline__ uint32_t h2(float a, float b) {   // pack 2 fp16 (RN)
    uint32_t r;
    asm("{.reg .b16 lo,hi; cvt.rn.f16.f32 lo,%1; cvt.rn.f16.f32 hi,%2; mov.b32 %0,{lo,hi};}"
        : "=r"(r) : "f"(a), "f"(b));
    return r;
}
__device__ __forceinline__ void mma_f16(float* c, const uint32_t* a, const uint32_t* b) {
    asm volatile(
        "mma.sync.aligned.m16n8k16.row.col.f32.f16.f16.f32 "
        "{%0,%1,%2,%3}, {%4,%5,%6,%7}, {%8,%9}, {%0,%1,%2,%3};\n"
        : "+f"(c[0]), "+f"(c[1]), "+f"(c[2]), "+f"(c[3])
        : "r"(a[0]), "r"(a[1]), "r"(a[2]), "r"(a[3]), "r"(b[0]), "r"(b[1]));
}
__device__ __forceinline__ void ldsm4(uint32_t& r0, uint32_t& r1, uint32_t& r2, uint32_t& r3,
                                      uint32_t a) {
    asm volatile("ldmatrix.sync.aligned.m8n8.x4.shared.b16 {%0,%1,%2,%3}, [%4];"
                 : "=r"(r0), "=r"(r1), "=r"(r2), "=r"(r3) : "r"(a));
}
__device__ __forceinline__ void ldsm4t(uint32_t& r0, uint32_t& r1, uint32_t& r2, uint32_t& r3,
                                       uint32_t a) {
    asm volatile("ldmatrix.sync.aligned.m8n8.x4.trans.shared.b16 {%0,%1,%2,%3}, [%4];"
                 : "=r"(r0), "=r"(r1), "=r"(r2), "=r"(r3) : "r"(a));
}
__device__ __forceinline__ uint32_t smem_u32(const void* p) {
    uint32_t a;
    asm("{ .reg .u64 t; cvta.to.shared.u64 t, %1; cvt.u32.u64 %0, t; }" : "=r"(a) : "l"(p));
    return a;
}
__device__ __forceinline__ void cpa16(uint32_t dst, const void* src) {
    asm volatile("cp.async.cg.shared.global [%0], [%1], 16;" :: "r"(dst), "l"(src));
}
__device__ __forceinline__ void cp_commit() { asm volatile("cp.async.commit_group;"); }
template <int N> __device__ __forceinline__ void cp_wait() {
    asm volatile("cp.async.wait_group %0;" :: "n"(N));
}
__device__ __forceinline__ void sts64(uint32_t a, uint32_t x, uint32_t y) {
    asm volatile("st.shared.v2.b32 [%0], {%1,%2};" :: "r"(a), "r"(x), "r"(y) : "memory");
}

// ---------------- small kernels ----------------
__global__ void zero_counts_kernel() { if (threadIdx.x < E) g_cnt[threadIdx.x] = 0; }

__global__ __launch_bounds__(256) void router_kernel(
    const float* __restrict__ x, const float* __restrict__ gw, float* __restrict__ logits_out) {
    __shared__ float sgw[E * H];
    int tid = threadIdx.x;
    for (int i = tid; i < E * H; i += 256) sgw[i] = gw[i];
    __syncthreads();
    int warp = tid >> 5, lane = tid & 31;
    int t = blockIdx.x * 8 + warp;
    float xr[32];
    const float* xp = x + (size_t)t * H;
#pragma unroll
    for (int i = 0; i < 32; i++) xr[i] = xp[i * 32 + lane];
    float l[E];
#pragma unroll
    for (int e = 0; e < E; e++) {
        float acc = 0.f;
        const float* g = sgw + e * H;
#pragma unroll
        for (int i = 0; i < 32; i++) acc += xr[i] * g[i * 32 + lane];
#pragma unroll
        for (int o = 16; o > 0; o >>= 1) acc += __shfl_xor_sync(0xffffffffu, acc, o);
        l[e] = acc;
    }
    if (lane == 0) {
#pragma unroll
        for (int e = 0; e < E; e++) logits_out[(size_t)t * E + e] = l[e];
        int e0 = 0; float b0 = l[0];
#pragma unroll
        for (int e = 1; e < E; e++) if (l[e] > b0) { b0 = l[e]; e0 = e; }
        int e1 = (e0 == 0) ? 1 : 0; float b1 = l[e1];
#pragma unroll
        for (int e = 0; e < E; e++) if (e != e0 && l[e] > b1) { b1 = l[e]; e1 = e; }
        float p = expf(b1 - b0), inv = 1.f / (1.f + p);
        g_top_e[2 * t] = e0;     g_top_w[2 * t] = inv;
        g_top_e[2 * t + 1] = e1; g_top_w[2 * t + 1] = p * inv;
        atomicAdd(&g_cnt[e0], 1);
        atomicAdd(&g_cnt[e1], 1);
    }
}

__global__ void scan_kernel() {
    int off = 0;
    for (int e = 0; e < E; e++) { g_off[e] = off; g_cur[e] = off; off += g_cnt[e]; }
}

__global__ void assign_kernel() {
    int t = blockIdx.x * blockDim.x + threadIdx.x;
    if (t >= T) return;
#pragma unroll
    for (int k = 0; k < 2; k++) {
        int e = g_top_e[2 * t + k];
        int slot = atomicAdd(&g_cur[e], 1);
        g_assign_tok[slot] = t;
        g_assign_w[slot] = g_top_w[2 * t + k];
        g_tok2slot[2 * t + k] = slot;
    }
}

// gather + fp16-round token rows once
__global__ void gather_kernel(const float* __restrict__ x) {
    int slot = blockIdx.x;
    int tok = g_assign_tok[slot];
    float4 f = ((const float4*)(x + (size_t)tok * H))[threadIdx.x];
    ((uint2*)(g_xh + (size_t)slot * H))[threadIdx.x] =
        make_uint2(h2(f.x, f.y), h2(f.z, f.w));
}

// ---------------------------------------------------------------------------
// GEMM tiles: CTA 512 thr (16 warps, 4x4), tile M=128 x N=128, K-stage 32,
// 3-stage cp.async ring. A fp16 [row][k] stride 40 halves; B fp16 [k][n]
// stride 136 halves (ldmatrix conflict-free). Frags via ldmatrix.x4(.trans).
// ---------------------------------------------------------------------------
constexpr int STG = 3;
constexpr int A_ST_B = 128 * 80;       // 10240 B per A stage (stride 40 halves)
constexpr int B_ST_B = 32 * 272;       // 8704 B per B stage (stride 136 halves)
constexpr int G1_SMEM = STG * A_ST_B + STG * 2 * B_ST_B;   // 82944
constexpr int G2_SMEM = STG * A_ST_B + STG * B_ST_B;       // 56832

// GEMM1: act = rw * silu(X@w1) * (X@w3)
__global__ void __launch_bounds__(512, 1) gemm1_kernel(
    const float* __restrict__ w1, const float* __restrict__ w3) {
    const int e = blockIdx.z, mt = blockIdx.y;
    const int cnt = g_cnt[e];
    if (mt * 128 >= cnt) return;
    const int off = g_off[e];
    const int n0 = blockIdx.x * 128;

    extern __shared__ uint8_t smb[];
    const uint32_t sb = smem_u32(smb);
    __shared__ float swt[128];

    const int tid = threadIdx.x;
    if (tid < 128) {
        int r = mt * 128 + tid;
        swt[tid] = (r < cnt) ? g_assign_w[off + r] : 0.f;
    }

    const __half* Ah = g_xh + (size_t)(off + mt * 128) * H;
    const float* w1p = w1 + (size_t)e * H * F + n0;
    const float* w3p = w3 + (size_t)e * H * F + n0;

    auto stage = [&](int s, int k0) {
        // A: 128 rows x 32 halves, cp.async 16B x512
        {
            int row = tid >> 2, c = tid & 3;
            cpa16(sb + s * A_ST_B + row * 80 + c * 16, Ah + (size_t)row * H + k0 + c * 8);
        }
        // B: 32 rows x 128 floats -> fp16, x2 matrices
        const uint32_t b1b = sb + STG * A_ST_B + s * B_ST_B;
        const uint32_t b3b = sb + STG * A_ST_B + (STG + s) * B_ST_B;
#pragma unroll
        for (int v = 0; v < 2; v++) {
            int idx = tid + v * 512;
            int row = idx >> 5, nn = (idx & 31) * 4;
            size_t g = (size_t)(k0 + row) * F + nn;
            float4 f1 = *(const float4*)(w1p + g);
            sts64(b1b + row * 272 + nn * 2, h2(f1.x, f1.y), h2(f1.z, f1.w));
            float4 f3 = *(const float4*)(w3p + g);
            sts64(b3b + row * 272 + nn * 2, h2(f3.x, f3.y), h2(f3.z, f3.w));
        }
        cp_commit();
    };

    const int lane = tid & 31, warp = tid >> 5;
    const int wm = warp >> 2, wn = warp & 3;      // 4x4 warp grid, 32x32 tiles
    const int lr = lane >> 2, lc = lane & 3;
    const int l15 = lane & 15, l16 = lane >> 4;

    float accG[2][4][4], accU[2][4][4];
#pragma unroll
    for (int i = 0; i < 2; i++)
#pragma unroll
        for (int j = 0; j < 4; j++)
#pragma unroll
            for (int c = 0; c < 4; c++) { accG[i][j][c] = 0.f; accU[i][j][c] = 0.f; }

    stage(0, 0);
    stage(1, 32);

    const int NK = H / 32;  // 32
    for (int i = 0; i < NK; i++) {
        cp_wait<STG - 2>();
        __syncthreads();
        int kn = i + STG - 1;
        if (kn < NK) stage(kn % STG, kn * 32);
        else cp_commit();

        int s = i % STG;
        const uint32_t Asm = sb + s * A_ST_B;
        const uint32_t B1sm = sb + STG * A_ST_B + s * B_ST_B;
        const uint32_t B3sm = sb + STG * A_ST_B + (STG + s) * B_ST_B;
#pragma unroll
        for (int kk = 0; kk < 2; kk++) {
            uint32_t a[2][4];
#pragma unroll
            for (int mi = 0; mi < 2; mi++)
                ldsm4(a[mi][0], a[mi][1], a[mi][2], a[mi][3],
                      Asm + (wm * 32 + mi * 16 + l15) * 80 + (kk * 16 + l16 * 8) * 2);
            uint32_t b1[2][4], b3[2][4];
#pragma unroll
            for (int np = 0; np < 2; np++) {
                uint32_t ba = (kk * 16 + l15) * 272 + (wn * 32 + np * 16 + l16 * 8) * 2;
                ldsm4t(b1[np][0], b1[np][1], b1[np][2], b1[np][3], B1sm + ba);
                ldsm4t(b3[np][0], b3[np][1], b3[np][2], b3[np][3], B3sm + ba);
            }
#pragma unroll
            for (int ni = 0; ni < 4; ni++) {
                int np = ni >> 1, pr = (ni & 1) * 2;
                uint32_t bb1[2] = { b1[np][pr], b1[np][pr + 1] };
                uint32_t bb3[2] = { b3[np][pr], b3[np][pr + 1] };
#pragma unroll
                for (int mi = 0; mi < 2; mi++) {
                    mma_f16(accG[mi][ni], a[mi], bb1);
                    mma_f16(accU[mi][ni], a[mi], bb3);
                }
            }
        }
    }

    // epilogue: act = rw * u * silu(g), stored fp16 (GEMM2 A)
#pragma unroll
    for (int mi = 0; mi < 2; mi++)
#pragma unroll
        for (int hf = 0; hf < 2; hf++) {
            int row = wm * 32 + mi * 16 + lr + hf * 8;
            int grow = mt * 128 + row;
            if (grow < cnt) {
                float w = swt[row];
                __half* dst = g_acth + (size_t)(off + grow) * F + n0;
#pragma unroll
                for (int ni = 0; ni < 4; ni++) {
                    int col = wn * 32 + ni * 8 + lc * 2;
                    float gg = accG[mi][ni][hf * 2], uu = accU[mi][ni][hf * 2];
                    float a0 = w * uu * (gg / (1.f + expf(-gg)));
                    gg = accG[mi][ni][hf * 2 + 1]; uu = accU[mi][ni][hf * 2 + 1];
                    float a1 = w * uu * (gg / (1.f + expf(-gg)));
                    *(uint32_t*)(dst + col) = h2(a0, a1);
                }
            }
        }
}

// GEMM2: y = act @ w2[e]; K=2816
__global__ void __launch_bounds__(512, 1) gemm2_kernel(const float* __restrict__ w2) {
    const int e = blockIdx.z, mt = blockIdx.y;
    const int cnt = g_cnt[e];
    if (mt * 128 >= cnt) return;
    const int off = g_off[e];
    const int n0 = blockIdx.x * 128;

    extern __shared__ uint8_t smb[];
    const uint32_t sb = smem_u32(smb);
    const int tid = threadIdx.x;

    const __half* Ah = g_acth + (size_t)(off + mt * 128) * F;
    const float* Wp = w2 + (size_t)e * F * H + n0;

    auto stage = [&](int s, int k0) {
        {
            int row = tid >> 2, c = tid & 3;
            cpa16(sb + s * A_ST_B + row * 80 + c * 16, Ah + (size_t)row * F + k0 + c * 8);
        }
        const uint32_t bb = sb + STG * A_ST_B + s * B_ST_B;
#pragma unroll
        for (int v = 0; v < 2; v++) {
            int idx = tid + v * 512;
            int row = idx >> 5, nn = (idx & 31) * 4;
            float4 f = *(const float4*)(Wp + (size_t)(k0 + row) * H + nn);
            sts64(bb + row * 272 + nn * 2, h2(f.x, f.y), h2(f.z, f.w));
        }
        cp_commit();
    };

    const int lane = tid & 31, warp = tid >> 5;
    const int wm = warp >> 2, wn = warp & 3;
    const int lr = lane >> 2, lc = lane & 3;
    const int l15 = lane & 15, l16 = lane >> 4;

    float acc[2][4][4];
#pragma unroll
    for (int i = 0; i < 2; i++)
#pragma unroll
        for (int j = 0; j < 4; j++)
#pragma unroll
            for (int c = 0; c < 4; c++) acc[i][j][c] = 0.f;

    stage(0, 0);
    stage(1, 32);

    const int NK = F / 32;  // 88
    for (int i = 0; i < NK; i++) {
        cp_wait<STG - 2>();
        __syncthreads();
        int kn = i + STG - 1;
        if (kn < NK) stage(kn % STG, kn * 32);
        else cp_commit();

        int s = i % STG;
        const uint32_t Asm = sb + s * A_ST_B;
        const uint32_t Bsm = sb + STG * A_ST_B + s * B_ST_B;
#pragma unroll
        for (int kk = 0; kk < 2; kk++) {
            uint32_t a[2][4];
#pragma unroll
            for (int mi = 0; mi < 2; mi++)
                ldsm4(a[mi][0], a[mi][1], a[mi][2], a[mi][3],
                      Asm + (wm * 32 + mi * 16 + l15) * 80 + (kk * 16 + l16 * 8) * 2);
            uint32_t b[2][4];
#pragma unroll
            for (int np = 0; np < 2; np++) {
                uint32_t ba = (kk * 16 + l15) * 272 + (wn * 32 + np * 16 + l16 * 8) * 2;
                ldsm4t(b[np][0], b[np][1], b[np][2], b[np][3], Bsm + ba);
            }
#pragma unroll
            for (int ni = 0; ni < 4; ni++) {
                int np = ni >> 1, pr = (ni & 1) * 2;
                uint32_t bb[2] = { b[np][pr], b[np][pr + 1] };
#pragma unroll
                for (int mi = 0; mi < 2; mi++) mma_f16(acc[mi][ni], a[mi], bb);
            }
        }
    }

#pragma unroll
    for (int mi = 0; mi < 2; mi++)
#pragma unroll
        for (int hf = 0; hf < 2; hf++) {
            int row = wm * 32 + mi * 16 + lr + hf * 8;
            int grow = mt * 128 + row;
            if (grow < cnt) {
                float* dst = g_y + (size_t)(off + grow) * H + n0;
#pragma unroll
                for (int ni = 0; ni < 4; ni++) {
                    int col = wn * 32 + ni * 8 + lc * 2;
                    *(float2*)(dst + col) =
                        make_float2(acc[mi][ni][hf * 2], acc[mi][ni][hf * 2 + 1]);
                }
            }
        }
}

// ---------------- combine ----------------
__global__ void combine_kernel(float* __restrict__ out) {
    int t = blockIdx.x;
    int s0 = g_tok2slot[2 * t], s1 = g_tok2slot[2 * t + 1];
    float4 a = ((const float4*)(g_y + (size_t)s0 * H))[threadIdx.x];
    float4 b = ((const float4*)(g_y + (size_t)s1 * H))[threadIdx.x];
    ((float4*)(out + (size_t)t * H))[threadIdx.x] =
        make_float4(a.x + b.x, a.y + b.y, a.z + b.z, a.w + b.w);
}

// ---------------- launch ----------------
extern "C" void kernel_launch(void* const* d_in, const int* in_sizes, int n_in,
                              void* d_out, int out_size) {
    const float* x  = (const float*)d_in[0];
    const float* gw = (const float*)d_in[1];
    const float* w1 = (const float*)d_in[2];
    const float* w3 = (const float*)d_in[3];
    const float* w2 = (const float*)d_in[4];
    float* out = (float*)d_out;

    float* logits;
    if (out_size >= T * H + T * E) logits = out + (size_t)T * H;
    else cudaGetSymbolAddress((void**)&logits, g_logits_dummy);

    cudaFuncSetAttribute(gemm1_kernel, cudaFuncAttributeMaxDynamicSharedMemorySize, G1_SMEM);
    cudaFuncSetAttribute(gemm2_kernel, cudaFuncAttributeMaxDynamicSharedMemorySize, G2_SMEM);

    zero_counts_kernel<<<1, 32>>>();
    router_kernel<<<T / 8, 256>>>(x, gw, logits);
    scan_kernel<<<1, 1>>>();
    assign_kernel<<<(T + 255) / 256, 256>>>();
    gather_kernel<<<AMAX, 256>>>(x);
    gemm1_kernel<<<dim3(F / 128, 16, E), 512, G1_SMEM>>>(w1, w3);
    gemm2_kernel<<<dim3(H / 128, 16, E), 512, G2_SMEM>>>(w2);
    combine_kernel<<<T, 256>>>(out);
}

// round 13
// speedup vs baseline: 1.6547x; 1.2004x over previous
#include <cuda_runtime.h>
#include <cuda_fp16.h>
#include <stdint.h>
#include <math.h>

// Mixtral sparse MoE, GB300 sm_103a. T=2048, H=1024, E=8, F=2816, top-2.
// fp16 mma.sync m16n8k16, fp32 accum. 256 thr/CTA (no spills), split-B staging.
constexpr int T = 2048, H = 1024, E = 8, F = 2816;
constexpr int AMAX = 2 * T, APAD = AMAX + 256;

__device__ __half g_xh[(size_t)APAD * H];     // gathered tokens, fp16
__device__ __half g_acth[(size_t)APAD * F];   // SwiGLU activations, fp16
__device__ float  g_y[(size_t)AMAX * H];      // per-slot down proj
__device__ int   g_cnt[E], g_off[E], g_cur[E];
__device__ int   g_top_e[T * 2];
__device__ float g_top_w[T * 2];
__device__ int   g_assign_tok[AMAX];
__device__ float g_assign_w[AMAX];
__device__ int   g_tok2slot[T * 2];
__device__ float g_logits_dummy[T * E];

// ---------------- helpers ----------------
__device__ __forceinline__ uint32_t h2(float a, float b) {   // pack 2 fp16 (RN)
    uint32_t r;
    asm("{.reg .b16 lo,hi; cvt.rn.f16.f32 lo,%1; cvt.rn.f16.f32 hi,%2; mov.b32 %0,{lo,hi};}"
        : "=r"(r) : "f"(a), "f"(b));
    return r;
}
__device__ __forceinline__ void mma_f16(float* c, const uint32_t* a, const uint32_t* b) {
    asm volatile(
        "mma.sync.aligned.m16n8k16.row.col.f32.f16.f16.f32 "
        "{%0,%1,%2,%3}, {%4,%5,%6,%7}, {%8,%9}, {%0,%1,%2,%3};\n"
        : "+f"(c[0]), "+f"(c[1]), "+f"(c[2]), "+f"(c[3])
        : "r"(a[0]), "r"(a[1]), "r"(a[2]), "r"(a[3]), "r"(b[0]), "r"(b[1]));
}
__device__ __forceinline__ void ldsm4(uint32_t& r0, uint32_t& r1, uint32_t& r2, uint32_t& r3,
                                      uint32_t a) {
    asm volatile("ldmatrix.sync.aligned.m8n8.x4.shared.b16 {%0,%1,%2,%3}, [%4];"
                 : "=r"(r0), "=r"(r1), "=r"(r2), "=r"(r3) : "r"(a));
}
__device__ __forceinline__ void ldsm4t(uint32_t& r0, uint32_t& r1, uint32_t& r2, uint32_t& r3,
                                       uint32_t a) {
    asm volatile("ldmatrix.sync.aligned.m8n8.x4.trans.shared.b16 {%0,%1,%2,%3}, [%4];"
                 : "=r"(r0), "=r"(r1), "=r"(r2), "=r"(r3) : "r"(a));
}
__device__ __forceinline__ uint32_t smem_u32(const void* p) {
    uint32_t a;
    asm("{ .reg .u64 t; cvta.to.shared.u64 t, %1; cvt.u32.u64 %0, t; }" : "=r"(a) : "l"(p));
    return a;
}
__device__ __forceinline__ void cpa16(uint32_t dst, const void* src) {
    asm volatile("cp.async.cg.shared.global [%0], [%1], 16;" :: "r"(dst), "l"(src));
}
__device__ __forceinline__ void cp_commit() { asm volatile("cp.async.commit_group;"); }
template <int N> __device__ __forceinline__ void cp_wait() {
    asm volatile("cp.async.wait_group %0;" :: "n"(N));
}
__device__ __forceinline__ void sts64(uint32_t a, uint32_t x, uint32_t y) {
    asm volatile("st.shared.v2.b32 [%0], {%1,%2};" :: "r"(a), "r"(x), "r"(y) : "memory");
}

// ---------------- small kernels ----------------
__global__ __launch_bounds__(256) void router_kernel(
    const float* __restrict__ x, const float* __restrict__ gw, float* __restrict__ logits_out) {
    __shared__ float sgw[E * H];
    int tid = threadIdx.x;
    for (int i = tid; i < E * H; i += 256) sgw[i] = gw[i];
    __syncthreads();
    int warp = tid >> 5, lane = tid & 31;
    int t = blockIdx.x * 8 + warp;
    float xr[32];
    const float* xp = x + (size_t)t * H;
#pragma unroll
    for (int i = 0; i < 32; i++) xr[i] = xp[i * 32 + lane];
    float l[E];
#pragma unroll
    for (int e = 0; e < E; e++) {
        float acc = 0.f;
        const float* g = sgw + e * H;
#pragma unroll
        for (int i = 0; i < 32; i++) acc += xr[i] * g[i * 32 + lane];
#pragma unroll
        for (int o = 16; o > 0; o >>= 1) acc += __shfl_xor_sync(0xffffffffu, acc, o);
        l[e] = acc;
    }
    if (lane == 0) {
#pragma unroll
        for (int e = 0; e < E; e++) logits_out[(size_t)t * E + e] = l[e];
        int e0 = 0; float b0 = l[0];
#pragma unroll
        for (int e = 1; e < E; e++) if (l[e] > b0) { b0 = l[e]; e0 = e; }
        int e1 = (e0 == 0) ? 1 : 0; float b1 = l[e1];
#pragma unroll
        for (int e = 0; e < E; e++) if (e != e0 && l[e] > b1) { b1 = l[e]; e1 = e; }
        float p = expf(b1 - b0), inv = 1.f / (1.f + p);
        g_top_e[2 * t] = e0;     g_top_w[2 * t] = inv;
        g_top_e[2 * t + 1] = e1; g_top_w[2 * t + 1] = p * inv;
        atomicAdd(&g_cnt[e0], 1);
        atomicAdd(&g_cnt[e1], 1);
    }
}

__global__ void scan_kernel() {
    int off = 0;
    for (int e = 0; e < E; e++) { g_off[e] = off; g_cur[e] = off; off += g_cnt[e]; }
}

// fused slot assignment + token gather (block per assignment)
__global__ __launch_bounds__(256) void assign_gather_kernel(const float* __restrict__ x) {
    __shared__ int s_slot, s_tok;
    int bid = blockIdx.x;                 // 0..AMAX-1  (= 2*t + k)
    if (threadIdx.x == 0) {
        int t = bid >> 1;
        int e = g_top_e[bid];
        int slot = atomicAdd(&g_cur[e], 1);
        g_assign_tok[slot] = t;
        g_assign_w[slot] = g_top_w[bid];
        g_tok2slot[bid] = slot;
        s_slot = slot; s_tok = t;
    }
    __syncthreads();
    int slot = s_slot, tok = s_tok;
    float4 f = ((const float4*)(x + (size_t)tok * H))[threadIdx.x];
    ((uint2*)(g_xh + (size_t)slot * H))[threadIdx.x] =
        make_uint2(h2(f.x, f.y), h2(f.z, f.w));
}

// ---------------------------------------------------------------------------
// GEMMs: 256 thr (8 warps, 2x4 grid, warp tile 64x32), CTA tile 128x128,
// K-stage 32, 3-buffer ring. A via cp.async (fp16 pre-converted); B via
// split LDG(regs) -> [compute] -> cvt+STS, hiding the L2 round-trip.
// A stride 40 halves, B stride 136 halves: conflict-free ldmatrix.
// ---------------------------------------------------------------------------
constexpr int A_ST_B = 128 * 80;       // 10240 B per A stage
constexpr int B_ST_B = 32 * 272;       // 8704 B per B stage
constexpr int G1_SMEM = 3 * (A_ST_B + 2 * B_ST_B);   // 82944
constexpr int G2_SMEM = 3 * (A_ST_B + B_ST_B);       // 56832

// GEMM1: act = rw * silu(X@w1) * (X@w3)
__global__ void __launch_bounds__(256, 1) gemm1_kernel(
    const float* __restrict__ w1, const float* __restrict__ w3) {
    const int e = blockIdx.z, mt = blockIdx.y;
    const int cnt = g_cnt[e];
    if (mt * 128 >= cnt) return;
    const int off = g_off[e];
    const int n0 = blockIdx.x * 128;

    extern __shared__ uint8_t smb[];
    const uint32_t sb = smem_u32(smb);
    __shared__ float swt[128];

    const int tid = threadIdx.x;
    if (tid < 128) {
        int r = mt * 128 + tid;
        swt[tid] = (r < cnt) ? g_assign_w[off + r] : 0.f;
    }

    const __half* Ah = g_xh + (size_t)(off + mt * 128) * H;
    const float* w1p = w1 + (size_t)e * H * F + n0;
    const float* w3p = w3 + (size_t)e * H * F + n0;

    uint4 br1[4], br3[4];
    auto ldgB = [&](int k0) {
#pragma unroll
        for (int v = 0; v < 4; v++) {
            int idx = tid + v * 256;
            int row = idx >> 5, nn = (idx & 31) * 4;
            size_t g = (size_t)(k0 + row) * F + nn;
            br1[v] = *(const uint4*)(w1p + g);
            br3[v] = *(const uint4*)(w3p + g);
        }
    };
    auto stsB = [&](int s) {
        const uint32_t b1b = sb + 3 * A_ST_B + s * B_ST_B;
        const uint32_t b3b = sb + 3 * A_ST_B + (3 + s) * B_ST_B;
#pragma unroll
        for (int v = 0; v < 4; v++) {
            int idx = tid + v * 256;
            int row = idx >> 5, nn = (idx & 31) * 4;
            float4 f1 = *(float4*)&br1[v];
            sts64(b1b + row * 272 + nn * 2, h2(f1.x, f1.y), h2(f1.z, f1.w));
            float4 f3 = *(float4*)&br3[v];
            sts64(b3b + row * 272 + nn * 2, h2(f3.x, f3.y), h2(f3.z, f3.w));
        }
    };
    auto cpA = [&](int s, int k0) {
#pragma unroll
        for (int v = 0; v < 2; v++) {
            int idx = tid + v * 256;
            int row = idx >> 2, c = idx & 3;
            cpa16(sb + s * A_ST_B + row * 80 + c * 16, Ah + (size_t)row * H + k0 + c * 8);
        }
        cp_commit();
    };

    const int lane = tid & 31, warp = tid >> 5;
    const int wm = warp >> 2, wn = warp & 3;     // 2x4 grid; warp tile 64x32
    const int lr = lane >> 2, lc = lane & 3;
    const int l15 = lane & 15, l16 = lane >> 4;

    float accG[4][4][4], accU[4][4][4];
#pragma unroll
    for (int i = 0; i < 4; i++)
#pragma unroll
        for (int j = 0; j < 4; j++)
#pragma unroll
            for (int c = 0; c < 4; c++) { accG[i][j][c] = 0.f; accU[i][j][c] = 0.f; }

    // prologue: stages 0,1 fully staged
    ldgB(0);  stsB(0); cpA(0, 0);
    ldgB(32); stsB(1); cpA(1, 32);
    cp_wait<1>();
    __syncthreads();

    const int NK = H / 32;  // 32
    for (int i = 0; i < NK; i++) {
        if (i + 2 < NK) ldgB((i + 2) * 32);   // in flight under compute

        int s = i % 3;
        const uint32_t Asm = sb + s * A_ST_B;
        const uint32_t B1sm = sb + 3 * A_ST_B + s * B_ST_B;
        const uint32_t B3sm = sb + 3 * A_ST_B + (3 + s) * B_ST_B;
#pragma unroll
        for (int kk = 0; kk < 2; kk++) {
            uint32_t a[4][4];
#pragma unroll
            for (int mi = 0; mi < 4; mi++)
                ldsm4(a[mi][0], a[mi][1], a[mi][2], a[mi][3],
                      Asm + (wm * 64 + mi * 16 + l15) * 80 + (kk * 16 + l16 * 8) * 2);
            uint32_t b1[2][4], b3[2][4];
#pragma unroll
            for (int np = 0; np < 2; np++) {
                uint32_t ba = (kk * 16 + l15) * 272 + (wn * 32 + np * 16 + l16 * 8) * 2;
                ldsm4t(b1[np][0], b1[np][1], b1[np][2], b1[np][3], B1sm + ba);
                ldsm4t(b3[np][0], b3[np][1], b3[np][2], b3[np][3], B3sm + ba);
            }
#pragma unroll
            for (int ni = 0; ni < 4; ni++) {
                int np = ni >> 1, pr = (ni & 1) * 2;
                uint32_t bb1[2] = { b1[np][pr], b1[np][pr + 1] };
                uint32_t bb3[2] = { b3[np][pr], b3[np][pr + 1] };
#pragma unroll
                for (int mi = 0; mi < 4; mi++) {
                    mma_f16(accG[mi][ni], a[mi], bb1);
                    mma_f16(accU[mi][ni], a[mi], bb3);
                }
            }
        }

        __syncthreads();                      // everyone done reading cell (i+2)%3
        if (i + 2 < NK) {
            stsB((i + 2) % 3);
            cpA((i + 2) % 3, (i + 2) * 32);
            cp_wait<1>();                     // A group i+1 done
        } else {
            cp_wait<0>();
        }
        __syncthreads();                      // staged data visible to all
    }

    // epilogue: act = rw * u * silu(g), stored fp16
#pragma unroll
    for (int mi = 0; mi < 4; mi++)
#pragma unroll
        for (int hf = 0; hf < 2; hf++) {
            int row = wm * 64 + mi * 16 + lr + hf * 8;
            int grow = mt * 128 + row;
            if (grow < cnt) {
                float w = swt[row];
                __half* dst = g_acth + (size_t)(off + grow) * F + n0;
#pragma unroll
                for (int ni = 0; ni < 4; ni++) {
                    int col = wn * 32 + ni * 8 + lc * 2;
                    float gg = accG[mi][ni][hf * 2], uu = accU[mi][ni][hf * 2];
                    float a0 = w * uu * (gg / (1.f + expf(-gg)));
                    gg = accG[mi][ni][hf * 2 + 1]; uu = accU[mi][ni][hf * 2 + 1];
                    float a1 = w * uu * (gg / (1.f + expf(-gg)));
                    *(uint32_t*)(dst + col) = h2(a0, a1);
                }
            }
        }
}

// GEMM2: y = act @ w2[e]; K=2816
__global__ void __launch_bounds__(256, 1) gemm2_kernel(const float* __restrict__ w2) {
    const int e = blockIdx.z, mt = blockIdx.y;
    const int cnt = g_cnt[e];
    if (mt * 128 >= cnt) return;
    const int off = g_off[e];
    const int n0 = blockIdx.x * 128;

    extern __shared__ uint8_t smb[];
    const uint32_t sb = smem_u32(smb);
    const int tid = threadIdx.x;

    const __half* Ah = g_acth + (size_t)(off + mt * 128) * F;
    const float* Wp = w2 + (size_t)e * F * H + n0;

    uint4 br[4];
    auto ldgB = [&](int k0) {
#pragma unroll
        for (int v = 0; v < 4; v++) {
            int idx = tid + v * 256;
            int row = idx >> 5, nn = (idx & 31) * 4;
            br[v] = *(const uint4*)(Wp + (size_t)(k0 + row) * H + nn);
        }
    };
    auto stsB = [&](int s) {
        const uint32_t bb = sb + 3 * A_ST_B + s * B_ST_B;
#pragma unroll
        for (int v = 0; v < 4; v++) {
            int idx = tid + v * 256;
            int row = idx >> 5, nn = (idx & 31) * 4;
            float4 f = *(float4*)&br[v];
            sts64(bb + row * 272 + nn * 2, h2(f.x, f.y), h2(f.z, f.w));
        }
    };
    auto cpA = [&](int s, int k0) {
#pragma unroll
        for (int v = 0; v < 2; v++) {
            int idx = tid + v * 256;
            int row = idx >> 2, c = idx & 3;
            cpa16(sb + s * A_ST_B + row * 80 + c * 16, Ah + (size_t)row * F + k0 + c * 8);
        }
        cp_commit();
    };

    const int lane = tid & 31, warp = tid >> 5;
    const int wm = warp >> 2, wn = warp & 3;
    const int lr = lane >> 2, lc = lane & 3;
    const int l15 = lane & 15, l16 = lane >> 4;

    float acc[4][4][4];
#pragma unroll
    for (int i = 0; i < 4; i++)
#pragma unroll
        for (int j = 0; j < 4; j++)
#pragma unroll
            for (int c = 0; c < 4; c++) acc[i][j][c] = 0.f;

    ldgB(0);  stsB(0); cpA(0, 0);
    ldgB(32); stsB(1); cpA(1, 32);
    cp_wait<1>();
    __syncthreads();

    const int NK = F / 32;  // 88
    for (int i = 0; i < NK; i++) {
        if (i + 2 < NK) ldgB((i + 2) * 32);

        int s = i % 3;
        const uint32_t Asm = sb + s * A_ST_B;
        const uint32_t Bsm = sb + 3 * A_ST_B + s * B_ST_B;
#pragma unroll
        for (int kk = 0; kk < 2; kk++) {
            uint32_t a[4][4];
#pragma unroll
            for (int mi = 0; mi < 4; mi++)
                ldsm4(a[mi][0], a[mi][1], a[mi][2], a[mi][3],
                      Asm + (wm * 64 + mi * 16 + l15) * 80 + (kk * 16 + l16 * 8) * 2);
            uint32_t b[2][4];
#pragma unroll
            for (int np = 0; np < 2; np++) {
                uint32_t ba = (kk * 16 + l15) * 272 + (wn * 32 + np * 16 + l16 * 8) * 2;
                ldsm4t(b[np][0], b[np][1], b[np][2], b[np][3], Bsm + ba);
            }
#pragma unroll
            for (int ni = 0; ni < 4; ni++) {
                int np = ni >> 1, pr = (ni & 1) * 2;
                uint32_t bb[2] = { b[np][pr], b[np][pr + 1] };
#pragma unroll
                for (int mi = 0; mi < 4; mi++) mma_f16(acc[mi][ni], a[mi], bb);
            }
        }

        __syncthreads();
        if (i + 2 < NK) {
            stsB((i + 2) % 3);
            cpA((i + 2) % 3, (i + 2) * 32);
            cp_wait<1>();
        } else {
            cp_wait<0>();
        }
        __syncthreads();
    }

#pragma unroll
    for (int mi = 0; mi < 4; mi++)
#pragma unroll
        for (int hf = 0; hf < 2; hf++) {
            int row = wm * 64 + mi * 16 + lr + hf * 8;
            int grow = mt * 128 + row;
            if (grow < cnt) {
                float* dst = g_y + (size_t)(off + grow) * H + n0;
#pragma unroll
                for (int ni = 0; ni < 4; ni++) {
                    int col = wn * 32 + ni * 8 + lc * 2;
                    *(float2*)(dst + col) =
                        make_float2(acc[mi][ni][hf * 2], acc[mi][ni][hf * 2 + 1]);
                }
            }
        }
}

// ---------------- combine (+ re-zero counts for the next graph replay) ------
__global__ void combine_kernel(float* __restrict__ out) {
    if (blockIdx.x == 0 && threadIdx.x < E) g_cnt[threadIdx.x] = 0;
    int t = blockIdx.x;
    int s0 = g_tok2slot[2 * t], s1 = g_tok2slot[2 * t + 1];
    float4 a = ((const float4*)(g_y + (size_t)s0 * H))[threadIdx.x];
    float4 b = ((const float4*)(g_y + (size_t)s1 * H))[threadIdx.x];
    ((float4*)(out + (size_t)t * H))[threadIdx.x] =
        make_float4(a.x + b.x, a.y + b.y, a.z + b.z, a.w + b.w);
}

// ---------------- launch ----------------
extern "C" void kernel_launch(void* const* d_in, const int* in_sizes, int n_in,
                              void* d_out, int out_size) {
    const float* x  = (const float*)d_in[0];
    const float* gw = (const float*)d_in[1];
    const float* w1 = (const float*)d_in[2];
    const float* w3 = (const float*)d_in[3];
    const float* w2 = (const float*)d_in[4];
    float* out = (float*)d_out;

    float* logits;
    if (out_size >= T * H + T * E) logits = out + (size_t)T * H;
    else cudaGetSymbolAddress((void**)&logits, g_logits_dummy);

    cudaFuncSetAttribute(gemm1_kernel, cudaFuncAttributeMaxDynamicSharedMemorySize, G1_SMEM);
    cudaFuncSetAttribute(gemm2_kernel, cudaFuncAttributeMaxDynamicSharedMemorySize, G2_SMEM);

    // g_cnt is zero on first run (static init) and re-zeroed by combine_kernel
    // at the end of every run, so each graph replay starts clean.
    router_kernel<<<T / 8, 256>>>(x, gw, logits);
    scan_kernel<<<1, 1>>>();
    assign_gather_kernel<<<AMAX, 256>>>(x);
    gemm1_kernel<<<dim3(F / 128, 16, E), 256, G1_SMEM>>>(w1, w3);
    gemm2_kernel<<<dim3(H / 128, 16, E), 256, G2_SMEM>>>(w2);
    combine_kernel<<<T, 256>>>(out);
}